// round 15
// baseline (speedup 1.0000x reference)
#include <cuda_runtime.h>
#include <cuda_fp16.h>
#include <cstdint>

// ---------------- problem constants ----------------
#define N_EMBD 1024
#define N_HEAD 16
#define DKH    64
#define BB     2
#define TT     2048
#define BT     (BB*TT)     // 4096 rows
#define C3     (3*N_EMBD)  // 3072

// scratch (allocation-free: device globals)
__device__ __half g_xh[BT * N_EMBD];       // x split hi
__device__ __half g_xl[BT * N_EMBD];       // x split lo
__device__ __half g_wah[C3 * N_EMBD];      // w_attn rounded
__device__ __half g_wph[N_EMBD * N_EMBD];  // w_proj rounded
__device__ __half g_qkvh[BT * C3];         // qkv split hi (Q pre-scaled 0.125)
__device__ __half g_qkvl[BT * C3];         // qkv split lo
__device__ __half g_atth[BT * N_EMBD];     // attention out hi
__device__ __half g_attl[BT * N_EMBD];     // attention out lo

// ---------------- fp16 helpers ----------------
__device__ __forceinline__ uint32_t packh2(__half a, __half b) {
    return (uint32_t)__half_as_ushort(a) | ((uint32_t)__half_as_ushort(b) << 16);
}
__device__ __forceinline__ void split2h(float f0, float f1, uint32_t& hi, uint32_t& lo) {
    __half h0 = __float2half_rn(f0);
    __half h1 = __float2half_rn(f1);
    float r0 = f0 - __half2float(h0);
    float r1 = f1 - __half2float(h1);
    hi = packh2(h0, h1);
    lo = packh2(__float2half_rn(r0), __float2half_rn(r1));
}
__device__ __forceinline__ uint32_t round2h(float f0, float f1) {
    return packh2(__float2half_rn(f0), __float2half_rn(f1));
}
__device__ __forceinline__ void mma_fp16(float d[4], const uint32_t a[4], const uint32_t b[2]) {
    asm volatile(
        "mma.sync.aligned.m16n8k16.row.col.f32.f16.f16.f32 "
        "{%0,%1,%2,%3}, {%4,%5,%6,%7}, {%8,%9}, {%0,%1,%2,%3};\n"
        : "+f"(d[0]), "+f"(d[1]), "+f"(d[2]), "+f"(d[3])
        : "r"(a[0]), "r"(a[1]), "r"(a[2]), "r"(a[3]),
          "r"(b[0]), "r"(b[1]));
}
__device__ __forceinline__ void ldsm_x4(uint32_t d[4], uint32_t addr) {
    asm volatile("ldmatrix.sync.aligned.m8n8.x4.shared.b16 {%0,%1,%2,%3}, [%4];"
                 : "=r"(d[0]), "=r"(d[1]), "=r"(d[2]), "=r"(d[3]) : "r"(addr));
}
__device__ __forceinline__ void ldm_x2_t(uint32_t& r0, uint32_t& r1, uint32_t addr) {
    asm volatile("ldmatrix.sync.aligned.m8n8.x2.trans.shared.b16 {%0,%1}, [%2];"
                 : "=r"(r0), "=r"(r1) : "r"(addr));
}
__device__ __forceinline__ void cp16(uint32_t dst, const void* src) {
    asm volatile("cp.async.cg.shared.global [%0], [%1], 16;" :: "r"(dst), "l"(src));
}
#define CP_COMMIT() asm volatile("cp.async.commit_group;" ::: "memory")
#define CP_WAIT(n)  asm volatile("cp.async.wait_group %0;" :: "n"(n) : "memory")

// ---------------- converters ----------------
__global__ __launch_bounds__(256) void conv_split(const float* __restrict__ in,
                                                  __half* __restrict__ oh,
                                                  __half* __restrict__ ol) {
    int i = (blockIdx.x * 256 + threadIdx.x) * 4;
    float4 v = *reinterpret_cast<const float4*>(in + i);
    uint32_t h01, l01, h23, l23;
    split2h(v.x, v.y, h01, l01);
    split2h(v.z, v.w, h23, l23);
    *reinterpret_cast<uint2*>(oh + i) = make_uint2(h01, h23);
    *reinterpret_cast<uint2*>(ol + i) = make_uint2(l01, l23);
}
__global__ __launch_bounds__(256) void conv_round(const float* __restrict__ in,
                                                  __half* __restrict__ oh) {
    int i = (blockIdx.x * 256 + threadIdx.x) * 4;
    float4 v = *reinterpret_cast<const float4*>(in + i);
    *reinterpret_cast<uint2*>(oh + i) = make_uint2(round2h(v.x, v.y), round2h(v.z, v.w));
}

// ---------------- pipelined fp16 NT GEMM (K-block 64, unchanged r14) ----------------
#define PBUF_B 55296
#define GEMM_SMEM (2 * PBUF_B)

template<bool SPLIT_OUT>
__global__ __launch_bounds__(256, 2) void gemm_h_pipe(const __half* __restrict__ Ah,
                                                      const __half* __restrict__ Al,
                                                      const __half* __restrict__ Bh,
                                                      float* __restrict__ Cf,
                                                      __half* __restrict__ Ch,
                                                      __half* __restrict__ Cl,
                                                      int M, int N, int K)
{
    extern __shared__ __half sh[];
    const int tid = threadIdx.x, wid = tid >> 5, lane = tid & 31;
    const int wm = wid >> 2, wn = wid & 3;
    const int r = lane >> 2, tg = lane & 3;
    const int m0 = blockIdx.y * 128, n0 = blockIdx.x * 128;
    const uint32_t sbase = (uint32_t)__cvta_generic_to_shared(sh);

    float acc[4][4][4] = {};

    const int nblk = K / 64;
    auto issue = [&](int i) {
        const int kt = i * 64;
        const uint32_t dbase = sbase + (uint32_t)(i & 1) * PBUF_B;
#pragma unroll
        for (int q = 0; q < 12; q++) {
            int c = q * 256 + tid;
            int t = c >> 10;
            int rem = c & 1023;
            int rr = rem >> 3;
            int ch = rem & 7;
            const __half* src =
                (t == 0 ? Ah + (size_t)(m0 + rr) * K :
                 t == 1 ? Al + (size_t)(m0 + rr) * K :
                          Bh + (size_t)(n0 + rr) * K) + kt + ch * 8;
            cp16(dbase + (uint32_t)(t * 18432 + rr * 144 + ch * 16), src);
        }
    };

    issue(0);
    CP_COMMIT();

    const int arow = (lane & 15);
    const int acol = ((lane >> 4) & 1) * 8;
    const int brow_off = ((lane >> 4) & 1) * 8 + (lane & 7);
    const int bcol = ((lane >> 3) & 1) * 8;

    for (int i = 0; i < nblk; i++) {
        if (i + 1 < nblk) {
            issue(i + 1);
            CP_COMMIT();
            CP_WAIT(1);
        } else {
            CP_WAIT(0);
        }
        __syncthreads();

        const uint32_t abase = sbase + (uint32_t)(i & 1) * PBUF_B;
#pragma unroll
        for (int s = 0; s < 4; s++) {
            const int ks = s * 16;
            uint32_t af_h[4][4], af_l[4][4];
#pragma unroll
            for (int ti = 0; ti < 4; ti++) {
                uint32_t ad = abase +
                    (uint32_t)((wm * 64 + ti * 16 + arow) * 144 + (ks + acol) * 2);
                ldsm_x4(af_h[ti], ad);
                ldsm_x4(af_l[ti], ad + 18432u);
            }
            uint32_t bf[4][2];
#pragma unroll
            for (int g = 0; g < 2; g++) {
                uint32_t bd = abase + 36864u +
                    (uint32_t)((wn * 32 + g * 16 + brow_off) * 144 + (ks + bcol) * 2);
                uint32_t d[4];
                ldsm_x4(d, bd);
                bf[2 * g][0] = d[0]; bf[2 * g][1] = d[1];
                bf[2 * g + 1][0] = d[2]; bf[2 * g + 1][1] = d[3];
            }
#pragma unroll
            for (int ti = 0; ti < 4; ti++)
#pragma unroll
                for (int j = 0; j < 4; j++) {
                    mma_fp16(acc[ti][j], af_h[ti], bf[j]);
                    mma_fp16(acc[ti][j], af_l[ti], bf[j]);
                }
        }
        __syncthreads();
    }

#pragma unroll
    for (int ti = 0; ti < 4; ti++) {
        size_t row0 = (size_t)(m0 + wm * 64 + ti * 16 + r);
#pragma unroll
        for (int j = 0; j < 4; j++) {
            int col = n0 + wn * 32 + j * 8 + 2 * tg;
            if (SPLIT_OUT) {
                float sc = (col < N_EMBD) ? 0.125f : 1.0f;   // pre-scale Q block
                uint32_t hu, lu;
                split2h(acc[ti][j][0] * sc, acc[ti][j][1] * sc, hu, lu);
                *reinterpret_cast<uint32_t*>(Ch + row0 * N + col) = hu;
                *reinterpret_cast<uint32_t*>(Cl + row0 * N + col) = lu;
                split2h(acc[ti][j][2] * sc, acc[ti][j][3] * sc, hu, lu);
                *reinterpret_cast<uint32_t*>(Ch + (row0 + 8) * N + col) = hu;
                *reinterpret_cast<uint32_t*>(Cl + (row0 + 8) * N + col) = lu;
            } else {
                *reinterpret_cast<float2*>(Cf + row0 * N + col) =
                    make_float2(acc[ti][j][0], acc[ti][j][1]);
                *reinterpret_cast<float2*>(Cf + (row0 + 8) * N + col) =
                    make_float2(acc[ti][j][2], acc[ti][j][3]);
            }
        }
    }
}

// ---------------- causal flash attention v4 ----------------
// q-tile 128: warp owns 16 full rows (all 64 cols). Warp-local softmax,
// P register-resident (C-frag == A-frag), 2 syncs/iter, cp.async double buffer.
// smem: Qh 0 (128*144), Ql 18432, buf{0,1} @36864: Kh/Vh/Vl 3x9216 -> 92160 B
#define Q2L   18432
#define A2B0  36864
#define A2SZ  27648
#define ATT_SMEM_BYTES 92160

__global__ __launch_bounds__(256) void attn_h4(const __half* __restrict__ qkvh,
                                               const __half* __restrict__ qkvl,
                                               __half* __restrict__ atth,
                                               __half* __restrict__ attl)
{
    extern __shared__ char smc[];
    const int tid  = threadIdx.x;
    const int wid  = tid >> 5, lane = tid & 31;
    const int r    = lane >> 2, tg  = lane & 3;
    const int qt   = (int)gridDim.x - 1 - (int)blockIdx.x;   // big tiles first
    const int bh_  = blockIdx.y;
    const int b    = bh_ >> 4, h = bh_ & 15;
    const uint32_t sbase = (uint32_t)__cvta_generic_to_shared(smc);

    const int srow = tid >> 2;          // 0..63 (KV staging)
    const int sch  = (tid & 3) * 2;     // chunk pairs 0,2,4,6

    auto issue_kv = [&](int kt) {
        const uint32_t dbase = sbase + A2B0 + (uint32_t)(kt & 1) * A2SZ;
        size_t rg = (size_t)(b * TT + kt * 64 + srow) * C3 + h * DKH;
        const __half* ks  = qkvh + rg + N_EMBD;
        const __half* vhs = qkvh + rg + 2 * N_EMBD;
        const __half* vls = qkvl + rg + 2 * N_EMBD;
        uint32_t d = dbase + (uint32_t)(srow * 144 + sch * 16);
        cp16(d,                ks  + sch * 8);
        cp16(d + 16,           ks  + sch * 8 + 8);
        cp16(d + 9216,         vhs + sch * 8);
        cp16(d + 9216 + 16,    vhs + sch * 8 + 8);
        cp16(d + 18432,        vls + sch * 8);
        cp16(d + 18432 + 16,   vls + sch * 8 + 8);
    };

    // prologue: stage Q (128 rows) + first K/V tile
    {
        int qrow = tid >> 1;            // 0..127
        int qc   = (tid & 1) * 4;       // chunk base 0 / 4
        size_t rg = (size_t)(b * TT + qt * 128 + qrow) * C3 + h * DKH;
        uint32_t d = sbase + (uint32_t)(qrow * 144 + qc * 16);
#pragma unroll
        for (int c = 0; c < 4; c++) {
            cp16(d + c * 16,       qkvh + rg + (qc + c) * 8);
            cp16(d + Q2L + c * 16, qkvl + rg + (qc + c) * 8);
        }
    }
    issue_kv(0);
    CP_COMMIT();
    CP_WAIT(0);
    __syncthreads();

    // hoist Q fragments (whole kernel): warp rows wid*16..+16
    const int arow = (lane & 15);
    const int acol = ((lane >> 4) & 1) * 8;
    uint32_t qhf[4][4], qlf[4][4];
#pragma unroll
    for (int s = 0; s < 4; s++) {
        uint32_t ad = sbase + (uint32_t)((wid * 16 + arow) * 144 + (s * 16 + acol) * 2);
        ldsm_x4(qhf[s], ad);
        ldsm_x4(qlf[s], ad + Q2L);
    }

    const int wrow_lo = qt * 128 + wid * 16;
    const int brow_off = ((lane >> 4) & 1) * 8 + (lane & 7);
    const int bcol = ((lane >> 3) & 1) * 8;
    float m0_ = -1e30f, m1_ = -1e30f, l0_ = 0.f, l1_ = 0.f;
    float oacc[8][4] = {};

    const int ktmax = 2 * qt + 1;
    for (int kt = 0; kt <= ktmax; kt++) {
        if (kt < ktmax) {
            issue_kv(kt + 1);
            CP_COMMIT();
            CP_WAIT(1);
        } else {
            CP_WAIT(0);
        }
        __syncthreads();   // B1: tile kt ready (also protects buffer writes above)

        if (kt * 64 <= wrow_lo + 15) {   // warp has unmasked columns in this tile
            const uint32_t kb_base = sbase + A2B0 + (uint32_t)(kt & 1) * A2SZ;
            const uint32_t vh_base = kb_base + 9216u;
            const uint32_t vl_base = kb_base + 18432u;

            // ---- S = Q K^T (16 rows x 64 cols per warp) ----
            float sacc[8][4] = {};
#pragma unroll
            for (int s = 0; s < 4; s++) {
#pragma unroll
                for (int g = 0; g < 4; g++) {
                    uint32_t bd = kb_base +
                        (uint32_t)((g * 16 + brow_off) * 144 + (s * 16 + bcol) * 2);
                    uint32_t d[4];
                    ldsm_x4(d, bd);
                    uint32_t b0[2] = { d[0], d[1] }, b1[2] = { d[2], d[3] };
                    mma_fp16(sacc[2 * g],     qhf[s], b0);
                    mma_fp16(sacc[2 * g],     qlf[s], b0);
                    mma_fp16(sacc[2 * g + 1], qhf[s], b1);
                    mma_fp16(sacc[2 * g + 1], qlf[s], b1);
                }
            }

            // ---- mask + warp-local softmax ----
            const int mg0 = wrow_lo + r;
            float mx0 = -1e30f, mx1 = -1e30f;
#pragma unroll
            for (int j = 0; j < 8; j++) {
                int ng = kt * 64 + j * 8 + 2 * tg;
                if (ng     > mg0)     sacc[j][0] = -1e30f;
                if (ng + 1 > mg0)     sacc[j][1] = -1e30f;
                if (ng     > mg0 + 8) sacc[j][2] = -1e30f;
                if (ng + 1 > mg0 + 8) sacc[j][3] = -1e30f;
                mx0 = fmaxf(mx0, fmaxf(sacc[j][0], sacc[j][1]));
                mx1 = fmaxf(mx1, fmaxf(sacc[j][2], sacc[j][3]));
            }
            mx0 = fmaxf(mx0, __shfl_xor_sync(0xffffffffu, mx0, 1));
            mx0 = fmaxf(mx0, __shfl_xor_sync(0xffffffffu, mx0, 2));
            mx1 = fmaxf(mx1, __shfl_xor_sync(0xffffffffu, mx1, 1));
            mx1 = fmaxf(mx1, __shfl_xor_sync(0xffffffffu, mx1, 2));
            float mn0 = fmaxf(m0_, mx0), mn1 = fmaxf(m1_, mx1);
            float cr0 = __expf(m0_ - mn0), cr1 = __expf(m1_ - mn1);
            m0_ = mn0; m1_ = mn1;
            float s0 = 0.f, s1 = 0.f;
#pragma unroll
            for (int j = 0; j < 8; j++) {
                sacc[j][0] = __expf(sacc[j][0] - mn0);
                sacc[j][1] = __expf(sacc[j][1] - mn0);
                sacc[j][2] = __expf(sacc[j][2] - mn1);
                sacc[j][3] = __expf(sacc[j][3] - mn1);
                s0 += sacc[j][0] + sacc[j][1];
                s1 += sacc[j][2] + sacc[j][3];
            }
            s0 += __shfl_xor_sync(0xffffffffu, s0, 1);
            s0 += __shfl_xor_sync(0xffffffffu, s0, 2);
            s1 += __shfl_xor_sync(0xffffffffu, s1, 1);
            s1 += __shfl_xor_sync(0xffffffffu, s1, 2);
            l0_ = l0_ * cr0 + s0;
            l1_ = l1_ * cr1 + s1;
#pragma unroll
            for (int j = 0; j < 8; j++) {
                oacc[j][0] *= cr0; oacc[j][1] *= cr0;
                oacc[j][2] *= cr1; oacc[j][3] *= cr1;
            }

            // ---- O += P V (P from registers; C-frag == A-frag) ----
#pragma unroll
            for (int g = 0; g < 4; g++) {
                uint32_t pah[4];
                pah[0] = round2h(sacc[2 * g][0],     sacc[2 * g][1]);
                pah[1] = round2h(sacc[2 * g][2],     sacc[2 * g][3]);
                pah[2] = round2h(sacc[2 * g + 1][0], sacc[2 * g + 1][1]);
                pah[3] = round2h(sacc[2 * g + 1][2], sacc[2 * g + 1][3]);
                uint32_t krow = (uint32_t)(g * 16 + (lane & 15));
#pragma unroll
                for (int j = 0; j < 8; j++) {
                    uint32_t vh0, vh1, vl0, vl1;
                    ldm_x2_t(vh0, vh1, vh_base + krow * 144u + (uint32_t)j * 16u);
                    ldm_x2_t(vl0, vl1, vl_base + krow * 144u + (uint32_t)j * 16u);
                    uint32_t bhf[2] = { vh0, vh1 }, blf[2] = { vl0, vl1 };
                    mma_fp16(oacc[j], pah, bhf);
                    mma_fp16(oacc[j], pah, blf);
                }
            }
        }
        __syncthreads();   // B4: all reads of buffer kt done before next overwrite
    }

    // epilogue: normalize, split to fp16 hi/lo, store
    {
        float inv0 = 1.f / l0_, inv1 = 1.f / l1_;
        size_t row0 = (size_t)(b * TT + qt * 128 + wid * 16 + r);
#pragma unroll
        for (int j = 0; j < 8; j++) {
            int col = h * DKH + j * 8 + 2 * tg;
            uint32_t hu, lu;
            split2h(oacc[j][0] * inv0, oacc[j][1] * inv0, hu, lu);
            *reinterpret_cast<uint32_t*>(atth + row0 * N_EMBD + col) = hu;
            *reinterpret_cast<uint32_t*>(attl + row0 * N_EMBD + col) = lu;
            split2h(oacc[j][2] * inv1, oacc[j][3] * inv1, hu, lu);
            *reinterpret_cast<uint32_t*>(atth + (row0 + 8) * N_EMBD + col) = hu;
            *reinterpret_cast<uint32_t*>(attl + (row0 + 8) * N_EMBD + col) = lu;
        }
    }
}

// ---------------- launch ----------------
extern "C" void kernel_launch(void* const* d_in, const int* in_sizes, int n_in,
                              void* d_out, int out_size)
{
    const float* x  = (const float*)d_in[0];   // [2,2048,1024]
    const float* wa = (const float*)d_in[1];   // [3072,1024]
    const float* wp = (const float*)d_in[2];   // [1024,1024]
    float* out = (float*)d_out;                // [2,2048,1024]

    __half *xh, *xl, *wah, *wph, *qkvh, *qkvl, *atth, *attl;
    cudaGetSymbolAddress((void**)&xh, g_xh);
    cudaGetSymbolAddress((void**)&xl, g_xl);
    cudaGetSymbolAddress((void**)&wah, g_wah);
    cudaGetSymbolAddress((void**)&wph, g_wph);
    cudaGetSymbolAddress((void**)&qkvh, g_qkvh);
    cudaGetSymbolAddress((void**)&qkvl, g_qkvl);
    cudaGetSymbolAddress((void**)&atth, g_atth);
    cudaGetSymbolAddress((void**)&attl, g_attl);

    cudaFuncSetAttribute(gemm_h_pipe<true>,
                         cudaFuncAttributeMaxDynamicSharedMemorySize, GEMM_SMEM);
    cudaFuncSetAttribute(gemm_h_pipe<false>,
                         cudaFuncAttributeMaxDynamicSharedMemorySize, GEMM_SMEM);
    cudaFuncSetAttribute(attn_h4,
                         cudaFuncAttributeMaxDynamicSharedMemorySize, ATT_SMEM_BYTES);

    // 0) precision prep
    conv_split<<<BT * N_EMBD / 1024, 256>>>(x, xh, xl);
    conv_round<<<C3 * N_EMBD / 1024, 256>>>(wa, wah);
    conv_round<<<N_EMBD * N_EMBD / 1024, 256>>>(wp, wph);

    // 1) fused QKV projection -> split fp16 (Q pre-scaled by 0.125)
    gemm_h_pipe<true><<<dim3(C3 / 128, BT / 128), 256, GEMM_SMEM>>>(
        xh, xl, wah, nullptr, qkvh, qkvl, BT, C3, N_EMBD);

    // 2) causal attention (q-tile 128, warp-local softmax)
    attn_h4<<<dim3(TT / 128, BB * N_HEAD), 256, ATT_SMEM_BYTES>>>(qkvh, qkvl, atth, attl);

    // 3) output projection -> fp32 out
    gemm_h_pipe<false><<<dim3(N_EMBD / 128, BT / 128), 256, GEMM_SMEM>>>(
        atth, attl, wph, out, nullptr, nullptr, BT, N_EMBD, N_EMBD);
}

// round 16
// speedup vs baseline: 1.0324x; 1.0324x over previous
#include <cuda_runtime.h>
#include <cuda_fp16.h>
#include <cstdint>

// ---------------- problem constants ----------------
#define N_EMBD 1024
#define N_HEAD 16
#define DKH    64
#define BB     2
#define TT     2048
#define BT     (BB*TT)     // 4096 rows
#define C3     (3*N_EMBD)  // 3072

// scratch (allocation-free: device globals)
__device__ __half g_xh[BT * N_EMBD];       // x split hi
__device__ __half g_xl[BT * N_EMBD];       // x split lo
__device__ __half g_wah[C3 * N_EMBD];      // w_attn rounded
__device__ __half g_wph[N_EMBD * N_EMBD];  // w_proj rounded
__device__ __half g_qkvh[BT * C3];         // qkv split hi (Q pre-scaled 0.125)
__device__ __half g_qkvl[BT * C3];         // qkv split lo
__device__ __half g_atth[BT * N_EMBD];     // attention out hi
__device__ __half g_attl[BT * N_EMBD];     // attention out lo

// ---------------- fp16 helpers ----------------
__device__ __forceinline__ uint32_t packh2(__half a, __half b) {
    return (uint32_t)__half_as_ushort(a) | ((uint32_t)__half_as_ushort(b) << 16);
}
__device__ __forceinline__ void split2h(float f0, float f1, uint32_t& hi, uint32_t& lo) {
    __half h0 = __float2half_rn(f0);
    __half h1 = __float2half_rn(f1);
    float r0 = f0 - __half2float(h0);
    float r1 = f1 - __half2float(h1);
    hi = packh2(h0, h1);
    lo = packh2(__float2half_rn(r0), __float2half_rn(r1));
}
__device__ __forceinline__ uint32_t round2h(float f0, float f1) {
    return packh2(__float2half_rn(f0), __float2half_rn(f1));
}
__device__ __forceinline__ void mma_fp16(float d[4], const uint32_t a[4], const uint32_t b[2]) {
    asm volatile(
        "mma.sync.aligned.m16n8k16.row.col.f32.f16.f16.f32 "
        "{%0,%1,%2,%3}, {%4,%5,%6,%7}, {%8,%9}, {%0,%1,%2,%3};\n"
        : "+f"(d[0]), "+f"(d[1]), "+f"(d[2]), "+f"(d[3])
        : "r"(a[0]), "r"(a[1]), "r"(a[2]), "r"(a[3]),
          "r"(b[0]), "r"(b[1]));
}
__device__ __forceinline__ void ldsm_x4(uint32_t d[4], uint32_t addr) {
    asm volatile("ldmatrix.sync.aligned.m8n8.x4.shared.b16 {%0,%1,%2,%3}, [%4];"
                 : "=r"(d[0]), "=r"(d[1]), "=r"(d[2]), "=r"(d[3]) : "r"(addr));
}
__device__ __forceinline__ void ldm_x2_t(uint32_t& r0, uint32_t& r1, uint32_t addr) {
    asm volatile("ldmatrix.sync.aligned.m8n8.x2.trans.shared.b16 {%0,%1}, [%2];"
                 : "=r"(r0), "=r"(r1) : "r"(addr));
}
__device__ __forceinline__ void cp16(uint32_t dst, const void* src) {
    asm volatile("cp.async.cg.shared.global [%0], [%1], 16;" :: "r"(dst), "l"(src));
}
#define CP_COMMIT() asm volatile("cp.async.commit_group;" ::: "memory")
#define CP_WAIT(n)  asm volatile("cp.async.wait_group %0;" :: "n"(n) : "memory")

// ---------------- converters ----------------
__global__ __launch_bounds__(256) void conv_split(const float* __restrict__ in,
                                                  __half* __restrict__ oh,
                                                  __half* __restrict__ ol) {
    int i = (blockIdx.x * 256 + threadIdx.x) * 4;
    float4 v = *reinterpret_cast<const float4*>(in + i);
    uint32_t h01, l01, h23, l23;
    split2h(v.x, v.y, h01, l01);
    split2h(v.z, v.w, h23, l23);
    *reinterpret_cast<uint2*>(oh + i) = make_uint2(h01, h23);
    *reinterpret_cast<uint2*>(ol + i) = make_uint2(l01, l23);
}
__global__ __launch_bounds__(256) void conv_round(const float* __restrict__ in,
                                                  __half* __restrict__ oh) {
    int i = (blockIdx.x * 256 + threadIdx.x) * 4;
    float4 v = *reinterpret_cast<const float4*>(in + i);
    *reinterpret_cast<uint2*>(oh + i) = make_uint2(round2h(v.x, v.y), round2h(v.z, v.w));
}

// ---------------- pipelined fp16 NT GEMM (K-block 64, unchanged r14) ----------------
#define PBUF_B 55296
#define GEMM_SMEM (2 * PBUF_B)

template<bool SPLIT_OUT>
__global__ __launch_bounds__(256, 2) void gemm_h_pipe(const __half* __restrict__ Ah,
                                                      const __half* __restrict__ Al,
                                                      const __half* __restrict__ Bh,
                                                      float* __restrict__ Cf,
                                                      __half* __restrict__ Ch,
                                                      __half* __restrict__ Cl,
                                                      int M, int N, int K)
{
    extern __shared__ __half sh[];
    const int tid = threadIdx.x, wid = tid >> 5, lane = tid & 31;
    const int wm = wid >> 2, wn = wid & 3;
    const int r = lane >> 2, tg = lane & 3;
    const int m0 = blockIdx.y * 128, n0 = blockIdx.x * 128;
    const uint32_t sbase = (uint32_t)__cvta_generic_to_shared(sh);

    float acc[4][4][4] = {};

    const int nblk = K / 64;
    auto issue = [&](int i) {
        const int kt = i * 64;
        const uint32_t dbase = sbase + (uint32_t)(i & 1) * PBUF_B;
#pragma unroll
        for (int q = 0; q < 12; q++) {
            int c = q * 256 + tid;
            int t = c >> 10;
            int rem = c & 1023;
            int rr = rem >> 3;
            int ch = rem & 7;
            const __half* src =
                (t == 0 ? Ah + (size_t)(m0 + rr) * K :
                 t == 1 ? Al + (size_t)(m0 + rr) * K :
                          Bh + (size_t)(n0 + rr) * K) + kt + ch * 8;
            cp16(dbase + (uint32_t)(t * 18432 + rr * 144 + ch * 16), src);
        }
    };

    issue(0);
    CP_COMMIT();

    const int arow = (lane & 15);
    const int acol = ((lane >> 4) & 1) * 8;
    const int brow_off = ((lane >> 4) & 1) * 8 + (lane & 7);
    const int bcol = ((lane >> 3) & 1) * 8;

    for (int i = 0; i < nblk; i++) {
        if (i + 1 < nblk) {
            issue(i + 1);
            CP_COMMIT();
            CP_WAIT(1);
        } else {
            CP_WAIT(0);
        }
        __syncthreads();

        const uint32_t abase = sbase + (uint32_t)(i & 1) * PBUF_B;
#pragma unroll
        for (int s = 0; s < 4; s++) {
            const int ks = s * 16;
            uint32_t af_h[4][4], af_l[4][4];
#pragma unroll
            for (int ti = 0; ti < 4; ti++) {
                uint32_t ad = abase +
                    (uint32_t)((wm * 64 + ti * 16 + arow) * 144 + (ks + acol) * 2);
                ldsm_x4(af_h[ti], ad);
                ldsm_x4(af_l[ti], ad + 18432u);
            }
            uint32_t bf[4][2];
#pragma unroll
            for (int g = 0; g < 2; g++) {
                uint32_t bd = abase + 36864u +
                    (uint32_t)((wn * 32 + g * 16 + brow_off) * 144 + (ks + bcol) * 2);
                uint32_t d[4];
                ldsm_x4(d, bd);
                bf[2 * g][0] = d[0]; bf[2 * g][1] = d[1];
                bf[2 * g + 1][0] = d[2]; bf[2 * g + 1][1] = d[3];
            }
#pragma unroll
            for (int ti = 0; ti < 4; ti++)
#pragma unroll
                for (int j = 0; j < 4; j++) {
                    mma_fp16(acc[ti][j], af_h[ti], bf[j]);
                    mma_fp16(acc[ti][j], af_l[ti], bf[j]);
                }
        }
        __syncthreads();
    }

#pragma unroll
    for (int ti = 0; ti < 4; ti++) {
        size_t row0 = (size_t)(m0 + wm * 64 + ti * 16 + r);
#pragma unroll
        for (int j = 0; j < 4; j++) {
            int col = n0 + wn * 32 + j * 8 + 2 * tg;
            if (SPLIT_OUT) {
                float sc = (col < N_EMBD) ? 0.125f : 1.0f;   // pre-scale Q block
                uint32_t hu, lu;
                split2h(acc[ti][j][0] * sc, acc[ti][j][1] * sc, hu, lu);
                *reinterpret_cast<uint32_t*>(Ch + row0 * N + col) = hu;
                *reinterpret_cast<uint32_t*>(Cl + row0 * N + col) = lu;
                split2h(acc[ti][j][2] * sc, acc[ti][j][3] * sc, hu, lu);
                *reinterpret_cast<uint32_t*>(Ch + (row0 + 8) * N + col) = hu;
                *reinterpret_cast<uint32_t*>(Cl + (row0 + 8) * N + col) = lu;
            } else {
                *reinterpret_cast<float2*>(Cf + row0 * N + col) =
                    make_float2(acc[ti][j][0], acc[ti][j][1]);
                *reinterpret_cast<float2*>(Cf + (row0 + 8) * N + col) =
                    make_float2(acc[ti][j][2], acc[ti][j][3]);
            }
        }
    }
}

// ---------------- causal flash attention v5 ----------------
// q-tile 64, CTA = 128 threads (4 warps), warp owns 16 full rows x 64 cols.
// Warp-local softmax, P register-resident, 2 syncs/iter, cp.async double buffer.
// smem: Qh 0 (64*144=9216), Ql 9216, buf{0,1} @18432: Kh/Vh/Vl 3x9216 -> 73728 B
#define Q5L   9216
#define A5B0  18432
#define A5SZ  27648
#define ATT_SMEM_BYTES 73728

__global__ __launch_bounds__(128, 3) void attn_h5(const __half* __restrict__ qkvh,
                                                  const __half* __restrict__ qkvl,
                                                  __half* __restrict__ atth,
                                                  __half* __restrict__ attl)
{
    extern __shared__ char smc[];
    const int tid  = threadIdx.x;
    const int wid  = tid >> 5, lane = tid & 31;
    const int r    = lane >> 2, tg  = lane & 3;
    const int qt   = (int)gridDim.x - 1 - (int)blockIdx.x;   // big tiles first
    const int bh_  = blockIdx.y;
    const int b    = bh_ >> 4, h = bh_ & 15;
    const uint32_t sbase = (uint32_t)__cvta_generic_to_shared(smc);

    const int srow = tid >> 1;          // 0..63 (staging row)
    const int sc0  = (tid & 1) * 4;     // chunk base 0 / 4

    auto issue_kv = [&](int kt) {
        const uint32_t dbase = sbase + A5B0 + (uint32_t)(kt & 1) * A5SZ;
        size_t rg = (size_t)(b * TT + kt * 64 + srow) * C3 + h * DKH;
        const __half* ks  = qkvh + rg + N_EMBD;
        const __half* vhs = qkvh + rg + 2 * N_EMBD;
        const __half* vls = qkvl + rg + 2 * N_EMBD;
        uint32_t d = dbase + (uint32_t)(srow * 144 + sc0 * 16);
#pragma unroll
        for (int c = 0; c < 4; c++) {
            cp16(d + c * 16,         ks  + (sc0 + c) * 8);
            cp16(d + 9216 + c * 16,  vhs + (sc0 + c) * 8);
            cp16(d + 18432 + c * 16, vls + (sc0 + c) * 8);
        }
    };

    // prologue: stage Q (64 rows, hi+lo) + first K/V tile
    {
        size_t rg = (size_t)(b * TT + qt * 64 + srow) * C3 + h * DKH;
        uint32_t d = sbase + (uint32_t)(srow * 144 + sc0 * 16);
#pragma unroll
        for (int c = 0; c < 4; c++) {
            cp16(d + c * 16,       qkvh + rg + (sc0 + c) * 8);
            cp16(d + Q5L + c * 16, qkvl + rg + (sc0 + c) * 8);
        }
    }
    issue_kv(0);
    CP_COMMIT();
    CP_WAIT(0);
    __syncthreads();

    // hoist Q fragments (whole kernel): warp rows wid*16..+16
    const int arow = (lane & 15);
    const int acol = ((lane >> 4) & 1) * 8;
    uint32_t qhf[4][4], qlf[4][4];
#pragma unroll
    for (int s = 0; s < 4; s++) {
        uint32_t ad = sbase + (uint32_t)((wid * 16 + arow) * 144 + (s * 16 + acol) * 2);
        ldsm_x4(qhf[s], ad);
        ldsm_x4(qlf[s], ad + Q5L);
    }

    const int wrow_lo = qt * 64 + wid * 16;
    const int brow_off = ((lane >> 4) & 1) * 8 + (lane & 7);
    const int bcol = ((lane >> 3) & 1) * 8;
    float m0_ = -1e30f, m1_ = -1e30f, l0_ = 0.f, l1_ = 0.f;
    float oacc[8][4] = {};

    for (int kt = 0; kt <= qt; kt++) {
        if (kt < qt) {
            issue_kv(kt + 1);
            CP_COMMIT();
            CP_WAIT(1);
        } else {
            CP_WAIT(0);
        }
        __syncthreads();   // B1: tile kt ready

        const uint32_t kb_base = sbase + A5B0 + (uint32_t)(kt & 1) * A5SZ;
        const uint32_t vh_base = kb_base + 9216u;
        const uint32_t vl_base = kb_base + 18432u;

        // ---- S = Q K^T (16 rows x 64 cols per warp) ----
        float sacc[8][4] = {};
#pragma unroll
        for (int s = 0; s < 4; s++) {
#pragma unroll
            for (int g = 0; g < 4; g++) {
                uint32_t bd = kb_base +
                    (uint32_t)((g * 16 + brow_off) * 144 + (s * 16 + bcol) * 2);
                uint32_t d[4];
                ldsm_x4(d, bd);
                uint32_t b0[2] = { d[0], d[1] }, b1[2] = { d[2], d[3] };
                mma_fp16(sacc[2 * g],     qhf[s], b0);
                mma_fp16(sacc[2 * g],     qlf[s], b0);
                mma_fp16(sacc[2 * g + 1], qhf[s], b1);
                mma_fp16(sacc[2 * g + 1], qlf[s], b1);
            }
        }

        // ---- mask + warp-local softmax ----
        const int mg0 = wrow_lo + r;
        float mx0 = -1e30f, mx1 = -1e30f;
#pragma unroll
        for (int j = 0; j < 8; j++) {
            int ng = kt * 64 + j * 8 + 2 * tg;
            if (ng     > mg0)     sacc[j][0] = -1e30f;
            if (ng + 1 > mg0)     sacc[j][1] = -1e30f;
            if (ng     > mg0 + 8) sacc[j][2] = -1e30f;
            if (ng + 1 > mg0 + 8) sacc[j][3] = -1e30f;
            mx0 = fmaxf(mx0, fmaxf(sacc[j][0], sacc[j][1]));
            mx1 = fmaxf(mx1, fmaxf(sacc[j][2], sacc[j][3]));
        }
        mx0 = fmaxf(mx0, __shfl_xor_sync(0xffffffffu, mx0, 1));
        mx0 = fmaxf(mx0, __shfl_xor_sync(0xffffffffu, mx0, 2));
        mx1 = fmaxf(mx1, __shfl_xor_sync(0xffffffffu, mx1, 1));
        mx1 = fmaxf(mx1, __shfl_xor_sync(0xffffffffu, mx1, 2));
        float mn0 = fmaxf(m0_, mx0), mn1 = fmaxf(m1_, mx1);
        float cr0 = __expf(m0_ - mn0), cr1 = __expf(m1_ - mn1);
        m0_ = mn0; m1_ = mn1;
        float s0 = 0.f, s1 = 0.f;
#pragma unroll
        for (int j = 0; j < 8; j++) {
            sacc[j][0] = __expf(sacc[j][0] - mn0);
            sacc[j][1] = __expf(sacc[j][1] - mn0);
            sacc[j][2] = __expf(sacc[j][2] - mn1);
            sacc[j][3] = __expf(sacc[j][3] - mn1);
            s0 += sacc[j][0] + sacc[j][1];
            s1 += sacc[j][2] + sacc[j][3];
        }
        s0 += __shfl_xor_sync(0xffffffffu, s0, 1);
        s0 += __shfl_xor_sync(0xffffffffu, s0, 2);
        s1 += __shfl_xor_sync(0xffffffffu, s1, 1);
        s1 += __shfl_xor_sync(0xffffffffu, s1, 2);
        l0_ = l0_ * cr0 + s0;
        l1_ = l1_ * cr1 + s1;
#pragma unroll
        for (int j = 0; j < 8; j++) {
            oacc[j][0] *= cr0; oacc[j][1] *= cr0;
            oacc[j][2] *= cr1; oacc[j][3] *= cr1;
        }

        // ---- O += P V (P from registers; C-frag == A-frag) ----
#pragma unroll
        for (int g = 0; g < 4; g++) {
            uint32_t pah[4];
            pah[0] = round2h(sacc[2 * g][0],     sacc[2 * g][1]);
            pah[1] = round2h(sacc[2 * g][2],     sacc[2 * g][3]);
            pah[2] = round2h(sacc[2 * g + 1][0], sacc[2 * g + 1][1]);
            pah[3] = round2h(sacc[2 * g + 1][2], sacc[2 * g + 1][3]);
            uint32_t krow = (uint32_t)(g * 16 + (lane & 15));
#pragma unroll
            for (int j = 0; j < 8; j++) {
                uint32_t vh0, vh1, vl0, vl1;
                ldm_x2_t(vh0, vh1, vh_base + krow * 144u + (uint32_t)j * 16u);
                ldm_x2_t(vl0, vl1, vl_base + krow * 144u + (uint32_t)j * 16u);
                uint32_t bhf[2] = { vh0, vh1 }, blf[2] = { vl0, vl1 };
                mma_fp16(oacc[j], pah, bhf);
                mma_fp16(oacc[j], pah, blf);
            }
        }
        __syncthreads();   // B4: all reads of buffer done before next overwrite
    }

    // epilogue: normalize, split to fp16 hi/lo, store
    {
        float inv0 = 1.f / l0_, inv1 = 1.f / l1_;
        size_t row0 = (size_t)(b * TT + qt * 64 + wid * 16 + r);
#pragma unroll
        for (int j = 0; j < 8; j++) {
            int col = h * DKH + j * 8 + 2 * tg;
            uint32_t hu, lu;
            split2h(oacc[j][0] * inv0, oacc[j][1] * inv0, hu, lu);
            *reinterpret_cast<uint32_t*>(atth + row0 * N_EMBD + col) = hu;
            *reinterpret_cast<uint32_t*>(attl + row0 * N_EMBD + col) = lu;
            split2h(oacc[j][2] * inv1, oacc[j][3] * inv1, hu, lu);
            *reinterpret_cast<uint32_t*>(atth + (row0 + 8) * N_EMBD + col) = hu;
            *reinterpret_cast<uint32_t*>(attl + (row0 + 8) * N_EMBD + col) = lu;
        }
    }
}

// ---------------- launch ----------------
extern "C" void kernel_launch(void* const* d_in, const int* in_sizes, int n_in,
                              void* d_out, int out_size)
{
    const float* x  = (const float*)d_in[0];   // [2,2048,1024]
    const float* wa = (const float*)d_in[1];   // [3072,1024]
    const float* wp = (const float*)d_in[2];   // [1024,1024]
    float* out = (float*)d_out;                // [2,2048,1024]

    __half *xh, *xl, *wah, *wph, *qkvh, *qkvl, *atth, *attl;
    cudaGetSymbolAddress((void**)&xh, g_xh);
    cudaGetSymbolAddress((void**)&xl, g_xl);
    cudaGetSymbolAddress((void**)&wah, g_wah);
    cudaGetSymbolAddress((void**)&wph, g_wph);
    cudaGetSymbolAddress((void**)&qkvh, g_qkvh);
    cudaGetSymbolAddress((void**)&qkvl, g_qkvl);
    cudaGetSymbolAddress((void**)&atth, g_atth);
    cudaGetSymbolAddress((void**)&attl, g_attl);

    cudaFuncSetAttribute(gemm_h_pipe<true>,
                         cudaFuncAttributeMaxDynamicSharedMemorySize, GEMM_SMEM);
    cudaFuncSetAttribute(gemm_h_pipe<false>,
                         cudaFuncAttributeMaxDynamicSharedMemorySize, GEMM_SMEM);
    cudaFuncSetAttribute(attn_h5,
                         cudaFuncAttributeMaxDynamicSharedMemorySize, ATT_SMEM_BYTES);

    // 0) precision prep
    conv_split<<<BT * N_EMBD / 1024, 256>>>(x, xh, xl);
    conv_round<<<C3 * N_EMBD / 1024, 256>>>(wa, wah);
    conv_round<<<N_EMBD * N_EMBD / 1024, 256>>>(wp, wph);

    // 1) fused QKV projection -> split fp16 (Q pre-scaled by 0.125)
    gemm_h_pipe<true><<<dim3(C3 / 128, BT / 128), 256, GEMM_SMEM>>>(
        xh, xl, wah, nullptr, qkvh, qkvl, BT, C3, N_EMBD);

    // 2) causal attention (q-tile 64, 4-warp CTAs, warp-local softmax)
    attn_h5<<<dim3(TT / 64, BB * N_HEAD), 128, ATT_SMEM_BYTES>>>(qkvh, qkvl, atth, attl);

    // 3) output projection -> fp32 out
    gemm_h_pipe<false><<<dim3(N_EMBD / 128, BT / 128), 256, GEMM_SMEM>>>(
        atth, attl, wph, out, nullptr, nullptr, BT, N_EMBD, N_EMBD);
}

// round 17
// speedup vs baseline: 1.1574x; 1.1211x over previous
#include <cuda_runtime.h>
#include <cuda_fp16.h>
#include <cstdint>

// ---------------- problem constants ----------------
#define N_EMBD 1024
#define N_HEAD 16
#define DKH    64
#define BB     2
#define TT     2048
#define BT     (BB*TT)     // 4096 rows
#define C3     (3*N_EMBD)  // 3072

// scratch (allocation-free: device globals)
__device__ __half g_xh[BT * N_EMBD];       // x split hi
__device__ __half g_xl[BT * N_EMBD];       // x split lo
__device__ __half g_wah[C3 * N_EMBD];      // w_attn rounded
__device__ __half g_wph[N_EMBD * N_EMBD];  // w_proj rounded
__device__ __half g_qkvh[BT * C3];         // qkv split hi (Q pre-scaled 0.125)
__device__ __half g_qkvl[BT * C3];         // qkv split lo
__device__ __half g_atth[BT * N_EMBD];     // attention out hi
__device__ __half g_attl[BT * N_EMBD];     // attention out lo

// ---------------- fp16 helpers ----------------
__device__ __forceinline__ uint32_t packh2(__half a, __half b) {
    return (uint32_t)__half_as_ushort(a) | ((uint32_t)__half_as_ushort(b) << 16);
}
__device__ __forceinline__ void split2h(float f0, float f1, uint32_t& hi, uint32_t& lo) {
    __half h0 = __float2half_rn(f0);
    __half h1 = __float2half_rn(f1);
    float r0 = f0 - __half2float(h0);
    float r1 = f1 - __half2float(h1);
    hi = packh2(h0, h1);
    lo = packh2(__float2half_rn(r0), __float2half_rn(r1));
}
__device__ __forceinline__ uint32_t round2h(float f0, float f1) {
    return packh2(__float2half_rn(f0), __float2half_rn(f1));
}
__device__ __forceinline__ void mma_fp16(float d[4], const uint32_t a[4], const uint32_t b[2]) {
    asm volatile(
        "mma.sync.aligned.m16n8k16.row.col.f32.f16.f16.f32 "
        "{%0,%1,%2,%3}, {%4,%5,%6,%7}, {%8,%9}, {%0,%1,%2,%3};\n"
        : "+f"(d[0]), "+f"(d[1]), "+f"(d[2]), "+f"(d[3])
        : "r"(a[0]), "r"(a[1]), "r"(a[2]), "r"(a[3]),
          "r"(b[0]), "r"(b[1]));
}
__device__ __forceinline__ void ldsm_x4(uint32_t d[4], uint32_t addr) {
    asm volatile("ldmatrix.sync.aligned.m8n8.x4.shared.b16 {%0,%1,%2,%3}, [%4];"
                 : "=r"(d[0]), "=r"(d[1]), "=r"(d[2]), "=r"(d[3]) : "r"(addr));
}
__device__ __forceinline__ void ldm_x2_t(uint32_t& r0, uint32_t& r1, uint32_t addr) {
    asm volatile("ldmatrix.sync.aligned.m8n8.x2.trans.shared.b16 {%0,%1}, [%2];"
                 : "=r"(r0), "=r"(r1) : "r"(addr));
}
__device__ __forceinline__ void cp16(uint32_t dst, const void* src) {
    asm volatile("cp.async.cg.shared.global [%0], [%1], 16;" :: "r"(dst), "l"(src));
}
#define CP_COMMIT() asm volatile("cp.async.commit_group;" ::: "memory")
#define CP_WAIT(n)  asm volatile("cp.async.wait_group %0;" :: "n"(n) : "memory")

// ---------------- converters ----------------
__global__ __launch_bounds__(256) void conv_split(const float* __restrict__ in,
                                                  __half* __restrict__ oh,
                                                  __half* __restrict__ ol) {
    int i = (blockIdx.x * 256 + threadIdx.x) * 4;
    float4 v = *reinterpret_cast<const float4*>(in + i);
    uint32_t h01, l01, h23, l23;
    split2h(v.x, v.y, h01, l01);
    split2h(v.z, v.w, h23, l23);
    *reinterpret_cast<uint2*>(oh + i) = make_uint2(h01, h23);
    *reinterpret_cast<uint2*>(ol + i) = make_uint2(l01, l23);
}
__global__ __launch_bounds__(256) void conv_round(const float* __restrict__ in,
                                                  __half* __restrict__ oh) {
    int i = (blockIdx.x * 256 + threadIdx.x) * 4;
    float4 v = *reinterpret_cast<const float4*>(in + i);
    *reinterpret_cast<uint2*>(oh + i) = make_uint2(round2h(v.x, v.y), round2h(v.z, v.w));
}

// ---------------- pipelined fp16 NT GEMM (K-block 64, unchanged r14) ----------------
#define PBUF_B 55296
#define GEMM_SMEM (2 * PBUF_B)

template<bool SPLIT_OUT>
__global__ __launch_bounds__(256, 2) void gemm_h_pipe(const __half* __restrict__ Ah,
                                                      const __half* __restrict__ Al,
                                                      const __half* __restrict__ Bh,
                                                      float* __restrict__ Cf,
                                                      __half* __restrict__ Ch,
                                                      __half* __restrict__ Cl,
                                                      int M, int N, int K)
{
    extern __shared__ __half sh[];
    const int tid = threadIdx.x, wid = tid >> 5, lane = tid & 31;
    const int wm = wid >> 2, wn = wid & 3;
    const int r = lane >> 2, tg = lane & 3;
    const int m0 = blockIdx.y * 128, n0 = blockIdx.x * 128;
    const uint32_t sbase = (uint32_t)__cvta_generic_to_shared(sh);

    float acc[4][4][4] = {};

    const int nblk = K / 64;
    auto issue = [&](int i) {
        const int kt = i * 64;
        const uint32_t dbase = sbase + (uint32_t)(i & 1) * PBUF_B;
#pragma unroll
        for (int q = 0; q < 12; q++) {
            int c = q * 256 + tid;
            int t = c >> 10;
            int rem = c & 1023;
            int rr = rem >> 3;
            int ch = rem & 7;
            const __half* src =
                (t == 0 ? Ah + (size_t)(m0 + rr) * K :
                 t == 1 ? Al + (size_t)(m0 + rr) * K :
                          Bh + (size_t)(n0 + rr) * K) + kt + ch * 8;
            cp16(dbase + (uint32_t)(t * 18432 + rr * 144 + ch * 16), src);
        }
    };

    issue(0);
    CP_COMMIT();

    const int arow = (lane & 15);
    const int acol = ((lane >> 4) & 1) * 8;
    const int brow_off = ((lane >> 4) & 1) * 8 + (lane & 7);
    const int bcol = ((lane >> 3) & 1) * 8;

    for (int i = 0; i < nblk; i++) {
        if (i + 1 < nblk) {
            issue(i + 1);
            CP_COMMIT();
            CP_WAIT(1);
        } else {
            CP_WAIT(0);
        }
        __syncthreads();

        const uint32_t abase = sbase + (uint32_t)(i & 1) * PBUF_B;
#pragma unroll
        for (int s = 0; s < 4; s++) {
            const int ks = s * 16;
            uint32_t af_h[4][4], af_l[4][4];
#pragma unroll
            for (int ti = 0; ti < 4; ti++) {
                uint32_t ad = abase +
                    (uint32_t)((wm * 64 + ti * 16 + arow) * 144 + (ks + acol) * 2);
                ldsm_x4(af_h[ti], ad);
                ldsm_x4(af_l[ti], ad + 18432u);
            }
            uint32_t bf[4][2];
#pragma unroll
            for (int g = 0; g < 2; g++) {
                uint32_t bd = abase + 36864u +
                    (uint32_t)((wn * 32 + g * 16 + brow_off) * 144 + (ks + bcol) * 2);
                uint32_t d[4];
                ldsm_x4(d, bd);
                bf[2 * g][0] = d[0]; bf[2 * g][1] = d[1];
                bf[2 * g + 1][0] = d[2]; bf[2 * g + 1][1] = d[3];
            }
#pragma unroll
            for (int ti = 0; ti < 4; ti++)
#pragma unroll
                for (int j = 0; j < 4; j++) {
                    mma_fp16(acc[ti][j], af_h[ti], bf[j]);
                    mma_fp16(acc[ti][j], af_l[ti], bf[j]);
                }
        }
        __syncthreads();
    }

#pragma unroll
    for (int ti = 0; ti < 4; ti++) {
        size_t row0 = (size_t)(m0 + wm * 64 + ti * 16 + r);
#pragma unroll
        for (int j = 0; j < 4; j++) {
            int col = n0 + wn * 32 + j * 8 + 2 * tg;
            if (SPLIT_OUT) {
                float sc = (col < N_EMBD) ? 0.125f : 1.0f;   // pre-scale Q block
                uint32_t hu, lu;
                split2h(acc[ti][j][0] * sc, acc[ti][j][1] * sc, hu, lu);
                *reinterpret_cast<uint32_t*>(Ch + row0 * N + col) = hu;
                *reinterpret_cast<uint32_t*>(Cl + row0 * N + col) = lu;
                split2h(acc[ti][j][2] * sc, acc[ti][j][3] * sc, hu, lu);
                *reinterpret_cast<uint32_t*>(Ch + (row0 + 8) * N + col) = hu;
                *reinterpret_cast<uint32_t*>(Cl + (row0 + 8) * N + col) = lu;
            } else {
                *reinterpret_cast<float2*>(Cf + row0 * N + col) =
                    make_float2(acc[ti][j][0], acc[ti][j][1]);
                *reinterpret_cast<float2*>(Cf + (row0 + 8) * N + col) =
                    make_float2(acc[ti][j][2], acc[ti][j][3]);
            }
        }
    }
}

// ---------------- causal flash attention (attn_h3 base; V single fp16) ----------------
// smem bytes (row stride 144): Qh 0, Ql 9216, buf{0,1} @18432: Kh+Vh 2x9216 each,
// Ph 55296, pmax 64512, psum 65024 -> 65536 total
#define AQH 0
#define AQL 9216
#define ABUF0 18432
#define ABUFSZ 18432
#define APH 55296
#define APMAX 64512
#define APSUM 65024
#define ATT_SMEM_BYTES 65536

__global__ __launch_bounds__(256) void attn_h6(const __half* __restrict__ qkvh,
                                               const __half* __restrict__ qkvl,
                                               __half* __restrict__ atth,
                                               __half* __restrict__ attl)
{
    extern __shared__ char smc[];
    uint32_t (*Ph)[36] = (uint32_t(*)[36])(smc + APH);
    float* pmax = (float*)(smc + APMAX);
    float* psum = (float*)(smc + APSUM);

    const int tid  = threadIdx.x;
    const int wid  = tid >> 5, lane = tid & 31;
    const int wm   = wid & 3,  wn   = wid >> 2;
    const int r    = lane >> 2, tg  = lane & 3;
    const int qt   = (int)gridDim.x - 1 - (int)blockIdx.x;   // big tiles first
    const int bh_  = blockIdx.y;
    const int b    = bh_ >> 4, h = bh_ & 15;
    const uint32_t sbase = (uint32_t)__cvta_generic_to_shared(smc);

    const int srow = tid >> 2;          // 0..63
    const int sch  = (tid & 3) * 2;     // chunk pairs 0,2,4,6

    auto issue_kv = [&](int kt) {
        const uint32_t dbase = sbase + ABUF0 + (uint32_t)(kt & 1) * ABUFSZ;
        size_t rg = (size_t)(b * TT + kt * 64 + srow) * C3 + h * DKH;
        const __half* ks  = qkvh + rg + N_EMBD;
        const __half* vhs = qkvh + rg + 2 * N_EMBD;
        uint32_t d = dbase + (uint32_t)(srow * 144 + sch * 16);
        cp16(d,               ks  + sch * 8);
        cp16(d + 16,          ks  + sch * 8 + 8);
        cp16(d + 9216,        vhs + sch * 8);
        cp16(d + 9216 + 16,   vhs + sch * 8 + 8);
    };

    // prologue: stage Q + first K/V tile
    {
        size_t rg = (size_t)(b * TT + qt * 64 + srow) * C3 + h * DKH;
        uint32_t d = sbase + (uint32_t)(srow * 144 + sch * 16);
        cp16(d,               qkvh + rg + sch * 8);
        cp16(d + 16,          qkvh + rg + sch * 8 + 8);
        cp16(d + AQL,         qkvl + rg + sch * 8);
        cp16(d + AQL + 16,    qkvl + rg + sch * 8 + 8);
    }
    issue_kv(0);
    CP_COMMIT();
    CP_WAIT(0);
    __syncthreads();

    // hoist Q fragments into registers (whole kernel)
    const int arow = (lane & 15);
    const int acol = ((lane >> 4) & 1) * 8;
    uint32_t qhf[4][4], qlf[4][4];
#pragma unroll
    for (int s = 0; s < 4; s++) {
        uint32_t ad = sbase + AQH +
            (uint32_t)((wm * 16 + arow) * 144 + (s * 16 + acol) * 2);
        ldsm_x4(qhf[s], ad);
        ldsm_x4(qlf[s], ad + AQL);
    }

    const int mr = wm * 16 + r;
    const int brow_off = ((lane >> 4) & 1) * 8 + (lane & 7);
    const int bcol = ((lane >> 3) & 1) * 8;
    float m0_ = -1e30f, m1_ = -1e30f, l0_ = 0.f, l1_ = 0.f;
    float oacc[4][4] = {};

    for (int kt = 0; kt <= qt; kt++) {
        if (kt < qt) {
            issue_kv(kt + 1);
            CP_COMMIT();
            CP_WAIT(1);
        } else {
            CP_WAIT(0);
        }
        __syncthreads();   // B1: tile kt ready

        const uint32_t kb_base = sbase + ABUF0 + (uint32_t)(kt & 1) * ABUFSZ;
        const uint32_t vh_base = kb_base + 9216u;

        // S = Q K^T  (Q split 2-term, K single fp16; K via ldsm)
        float sacc[4][4] = {};
#pragma unroll
        for (int s = 0; s < 4; s++) {
            uint32_t bf[4][2];
#pragma unroll
            for (int g = 0; g < 2; g++) {
                uint32_t bd = kb_base +
                    (uint32_t)((wn * 32 + g * 16 + brow_off) * 144 + (s * 16 + bcol) * 2);
                uint32_t d[4];
                ldsm_x4(d, bd);
                bf[2 * g][0] = d[0]; bf[2 * g][1] = d[1];
                bf[2 * g + 1][0] = d[2]; bf[2 * g + 1][1] = d[3];
            }
#pragma unroll
            for (int j = 0; j < 4; j++) {
                mma_fp16(sacc[j], qhf[s], bf[j]);
                mma_fp16(sacc[j], qlf[s], bf[j]);
            }
        }

        // mask + per-row max (warp partial)
        const int mg0 = qt * 64 + mr;
        float mx0 = -1e30f, mx1 = -1e30f;
#pragma unroll
        for (int j = 0; j < 4; j++) {
            int ng = kt * 64 + wn * 32 + j * 8 + 2 * tg;
            if (ng     > mg0)     sacc[j][0] = -1e30f;
            if (ng + 1 > mg0)     sacc[j][1] = -1e30f;
            if (ng     > mg0 + 8) sacc[j][2] = -1e30f;
            if (ng + 1 > mg0 + 8) sacc[j][3] = -1e30f;
            mx0 = fmaxf(mx0, fmaxf(sacc[j][0], sacc[j][1]));
            mx1 = fmaxf(mx1, fmaxf(sacc[j][2], sacc[j][3]));
        }
        mx0 = fmaxf(mx0, __shfl_xor_sync(0xffffffffu, mx0, 1));
        mx0 = fmaxf(mx0, __shfl_xor_sync(0xffffffffu, mx0, 2));
        mx1 = fmaxf(mx1, __shfl_xor_sync(0xffffffffu, mx1, 1));
        mx1 = fmaxf(mx1, __shfl_xor_sync(0xffffffffu, mx1, 2));
        if (tg == 0) {
            pmax[wn * 64 + mr]     = mx0;
            pmax[wn * 64 + mr + 8] = mx1;
        }
        __syncthreads();   // B2

        float mn0 = fmaxf(m0_, fmaxf(pmax[mr],     pmax[64 + mr]));
        float mn1 = fmaxf(m1_, fmaxf(pmax[mr + 8], pmax[64 + mr + 8]));
        float cr0 = __expf(m0_ - mn0), cr1 = __expf(m1_ - mn1);
        m0_ = mn0; m1_ = mn1;
        float s0 = 0.f, s1 = 0.f;
#pragma unroll
        for (int j = 0; j < 4; j++) {
            float p0 = __expf(sacc[j][0] - mn0), p1 = __expf(sacc[j][1] - mn0);
            float p2 = __expf(sacc[j][2] - mn1), p3 = __expf(sacc[j][3] - mn1);
            s0 += p0 + p1; s1 += p2 + p3;
            int ci = wn * 16 + j * 4 + tg;
            Ph[mr][ci]     = round2h(p0, p1);
            Ph[mr + 8][ci] = round2h(p2, p3);
        }
        s0 += __shfl_xor_sync(0xffffffffu, s0, 1);
        s0 += __shfl_xor_sync(0xffffffffu, s0, 2);
        s1 += __shfl_xor_sync(0xffffffffu, s1, 1);
        s1 += __shfl_xor_sync(0xffffffffu, s1, 2);
        if (tg == 0) {
            psum[wn * 64 + mr]     = s0;
            psum[wn * 64 + mr + 8] = s1;
        }
        __syncthreads();   // B3

        l0_ = l0_ * cr0 + psum[mr]     + psum[64 + mr];
        l1_ = l1_ * cr1 + psum[mr + 8] + psum[64 + mr + 8];
#pragma unroll
        for (int j = 0; j < 4; j++) {
            oacc[j][0] *= cr0; oacc[j][1] *= cr0;
            oacc[j][2] *= cr1; oacc[j][3] *= cr1;
        }

        // O += P @ V (P single fp16, V single fp16: 1 mma per k16)
#pragma unroll
        for (int kb = 0; kb < 32; kb += 8) {
            uint32_t pah[4];
            pah[0] = Ph[mr][kb + tg];
            pah[1] = Ph[mr + 8][kb + tg];
            pah[2] = Ph[mr][kb + tg + 4];
            pah[3] = Ph[mr + 8][kb + tg + 4];
            int krow = kb * 2 + (lane & 15);
#pragma unroll
            for (int j = 0; j < 4; j++) {
                int c0j = wn * 32 + j * 8;
                uint32_t vh0, vh1;
                ldm_x2_t(vh0, vh1, vh_base + (uint32_t)(krow * 144 + c0j * 2));
                uint32_t bhf[2] = { vh0, vh1 };
                mma_fp16(oacc[j], pah, bhf);
            }
        }
        __syncthreads();   // B4: buffer reads done before next issue overwrites
    }

    // epilogue: normalize, split to fp16 hi/lo, store
    {
        float inv0 = 1.f / l0_, inv1 = 1.f / l1_;
        size_t row0 = (size_t)(b * TT + qt * 64 + mr);
#pragma unroll
        for (int j = 0; j < 4; j++) {
            int col = h * DKH + wn * 32 + j * 8 + 2 * tg;
            uint32_t hu, lu;
            split2h(oacc[j][0] * inv0, oacc[j][1] * inv0, hu, lu);
            *reinterpret_cast<uint32_t*>(atth + row0 * N_EMBD + col) = hu;
            *reinterpret_cast<uint32_t*>(attl + row0 * N_EMBD + col) = lu;
            split2h(oacc[j][2] * inv1, oacc[j][3] * inv1, hu, lu);
            *reinterpret_cast<uint32_t*>(atth + (row0 + 8) * N_EMBD + col) = hu;
            *reinterpret_cast<uint32_t*>(attl + (row0 + 8) * N_EMBD + col) = lu;
        }
    }
}

// ---------------- launch ----------------
extern "C" void kernel_launch(void* const* d_in, const int* in_sizes, int n_in,
                              void* d_out, int out_size)
{
    const float* x  = (const float*)d_in[0];   // [2,2048,1024]
    const float* wa = (const float*)d_in[1];   // [3072,1024]
    const float* wp = (const float*)d_in[2];   // [1024,1024]
    float* out = (float*)d_out;                // [2,2048,1024]

    __half *xh, *xl, *wah, *wph, *qkvh, *qkvl, *atth, *attl;
    cudaGetSymbolAddress((void**)&xh, g_xh);
    cudaGetSymbolAddress((void**)&xl, g_xl);
    cudaGetSymbolAddress((void**)&wah, g_wah);
    cudaGetSymbolAddress((void**)&wph, g_wph);
    cudaGetSymbolAddress((void**)&qkvh, g_qkvh);
    cudaGetSymbolAddress((void**)&qkvl, g_qkvl);
    cudaGetSymbolAddress((void**)&atth, g_atth);
    cudaGetSymbolAddress((void**)&attl, g_attl);

    cudaFuncSetAttribute(gemm_h_pipe<true>,
                         cudaFuncAttributeMaxDynamicSharedMemorySize, GEMM_SMEM);
    cudaFuncSetAttribute(gemm_h_pipe<false>,
                         cudaFuncAttributeMaxDynamicSharedMemorySize, GEMM_SMEM);
    cudaFuncSetAttribute(attn_h6,
                         cudaFuncAttributeMaxDynamicSharedMemorySize, ATT_SMEM_BYTES);

    // 0) precision prep
    conv_split<<<BT * N_EMBD / 1024, 256>>>(x, xh, xl);
    conv_round<<<C3 * N_EMBD / 1024, 256>>>(wa, wah);
    conv_round<<<N_EMBD * N_EMBD / 1024, 256>>>(wp, wph);

    // 1) fused QKV projection -> split fp16 (Q pre-scaled by 0.125)
    gemm_h_pipe<true><<<dim3(C3 / 128, BT / 128), 256, GEMM_SMEM>>>(
        xh, xl, wah, nullptr, qkvh, qkvl, BT, C3, N_EMBD);

    // 2) causal attention (V single fp16 in PV)
    attn_h6<<<dim3(TT / 64, BB * N_HEAD), 256, ATT_SMEM_BYTES>>>(qkvh, qkvl, atth, attl);

    // 3) output projection -> fp32 out
    gemm_h_pipe<false><<<dim3(N_EMBD / 128, BT / 128), 256, GEMM_SMEM>>>(
        atth, attl, wph, out, nullptr, nullptr, BT, N_EMBD, N_EMBD);
}